// round 8
// baseline (speedup 1.0000x reference)
#include <cuda_runtime.h>
#include <cuda_bf16.h>
#include <math.h>
#include <stdint.h>

#define BB   8192
#define NX   2048
#define NH   512
#define NY   1024

// Scratch (no allocations allowed in kernel_launch)
__device__ __nv_bfloat16 g_xb[(size_t)BB * NX];    // relu(x) in bf16
__device__ __nv_bfloat16 g_wfcb[(size_t)NH * NX];  // W_fc in bf16
__device__ __nv_bfloat16 g_wqb[(size_t)NY * NH];   // W_q in bf16
__device__ __nv_bfloat16 g_hb[(size_t)BB * NH];    // hidden activations bf16
__device__ float g_hnorm[BB];                      // ||h_i||^2
__device__ float g_wqnorm[NY];                     // ||w_j||^2

// ---------------------------------------------------------------------------
static __device__ __forceinline__ uint32_t smem_u32(const void* p) {
    uint32_t a;
    asm("{ .reg .u64 t; cvta.to.shared.u64 t, %1; cvt.u32.u64 %0, t; }"
        : "=r"(a) : "l"(p));
    return a;
}

#define LDSM_X4(r0, r1, r2, r3, a)                                           \
    asm volatile("ldmatrix.sync.aligned.m8n8.x4.shared.b16 {%0,%1,%2,%3}, [%4];" \
                 : "=r"(r0), "=r"(r1), "=r"(r2), "=r"(r3) : "r"(a))

#define CP16(s, g)                                                           \
    asm volatile("cp.async.cg.shared.global [%0], [%1], 16;" :: "r"(s), "l"(g))
#define CP_COMMIT() asm volatile("cp.async.commit_group;" ::: "memory")
#define CP_WAIT1()  asm volatile("cp.async.wait_group 1;"  ::: "memory")

static __device__ __forceinline__ void mma16(float* c, const uint32_t* a,
                                             uint32_t b0, uint32_t b1) {
    asm volatile(
        "mma.sync.aligned.m16n8k16.row.col.f32.bf16.bf16.f32 "
        "{%0,%1,%2,%3}, {%4,%5,%6,%7}, {%8,%9}, {%0,%1,%2,%3};"
        : "+f"(c[0]), "+f"(c[1]), "+f"(c[2]), "+f"(c[3])
        : "r"(a[0]), "r"(a[1]), "r"(a[2]), "r"(a[3]), "r"(b0), "r"(b1));
}

static __device__ __forceinline__ uint32_t pack_bf16(float lo, float hi) {
    __nv_bfloat162 v = __floats2bfloat162_rn(lo, hi);  // .x = low half
    return *(uint32_t*)&v;
}

// ---------------------------------------------------------------------------
// bf16 mma.sync GEMM-NT, cp.async 3-stage pipeline, 4 warps, warp tile 64x64.
// C[m][n] = epi( sum_k A[m][k] * B[n][k] ), A/B bf16 K-major.
// CTA tile 128x128, BK=64 (128B bf16 rows, SW128 swizzle), warps 2m x 2n.
// EPI==1: C(bf16) = relu(acc + prm[n])
// EPI==2: C(f32)  = -log1p(max(rown[m] - 2*acc + prm[n], 0))
// ---------------------------------------------------------------------------
#define TILE_BYTES  16384               // 128 rows x 128B
#define STAGE_BYTES 32768               // A + B
#define NSTAGE      3
#define DSMEM_BYTES (NSTAGE * STAGE_BYTES)

template<int EPI>
__global__ __launch_bounds__(128, 2)
void tgemm(const __nv_bfloat16* __restrict__ A, const __nv_bfloat16* __restrict__ Bm,
           const float* __restrict__ prm, const float* __restrict__ rown,
           void* __restrict__ Cv, int M, int N, int K)
{
    extern __shared__ char smem[];
    const uint32_t sbase = smem_u32(smem);

    const int tid  = threadIdx.x;
    const int bn   = blockIdx.x, bm = blockIdx.y;
    const int warp = tid >> 5, lane = tid & 31;
    const int wm   = warp & 1;          // 0..1 : 64-row slice
    const int wn   = warp >> 1;         // 0..1 : 64-col slice
    const int rm   = lane & 7;

    // ldmatrix row indices (proven geometry, 128B rows)
    const int kha = lane >> 4;
    const int khb = (lane >> 3) & 1;
    int rowA[4], rowB[4];
    #pragma unroll
    for (int mi = 0; mi < 4; mi++)
        rowA[mi] = wm * 64 + mi * 16 + ((lane >> 3) & 1) * 8 + rm;
    #pragma unroll
    for (int pp = 0; pp < 4; pp++)
        rowB[pp] = wn * 64 + pp * 16 + ((lane >> 4) & 1) * 8 + rm;

    float acc[4][8][4];
    #pragma unroll
    for (int i = 0; i < 4; i++)
        #pragma unroll
        for (int j = 0; j < 8; j++)
            #pragma unroll
            for (int q = 0; q < 4; q++) acc[i][j][q] = 0.f;

    const int KT = K >> 6;              // chunks of BK=64

    // loader (128 threads): r0 = row base (0..15), c4 = 16B chunk (8 bf16)
    const int r0 = tid >> 3;
    const int c4 = tid & 7;

    auto issue_copy = [&](int kt, int buf) {
        const uint32_t sa = sbase + buf * STAGE_BYTES;
        const uint32_t sb = sa + TILE_BYTES;
        const __nv_bfloat16* ag = A  + (size_t)(bm * 128 + r0) * K + kt * 64 + c4 * 8;
        const __nv_bfloat16* bg = Bm + (size_t)(bn * 128 + r0) * K + kt * 64 + c4 * 8;
        #pragma unroll
        for (int p = 0; p < 8; p++) {
            const int row = r0 + p * 16;
            const uint32_t soff = row * 128 + ((c4 ^ (row & 7)) * 16);
            CP16(sa + soff, ag + (size_t)p * 16 * K);
            CP16(sb + soff, bg + (size_t)p * 16 * K);
        }
    };

    auto compute = [&](int buf) {
        const uint32_t Sa = sbase + buf * STAGE_BYTES;
        const uint32_t Sb = Sa + TILE_BYTES;
        #pragma unroll
        for (int ks = 0; ks < 4; ks++) {       // k16 steps within BK=64
            uint32_t a[4][4], b[4][4];
            #pragma unroll
            for (int mi = 0; mi < 4; mi++) {
                const uint32_t addr = Sa + rowA[mi] * 128 + (((2*ks + kha) ^ rm) * 16);
                LDSM_X4(a[mi][0], a[mi][1], a[mi][2], a[mi][3], addr);
            }
            #pragma unroll
            for (int pp = 0; pp < 4; pp++) {
                const uint32_t addr = Sb + rowB[pp] * 128 + (((2*ks + khb) ^ rm) * 16);
                LDSM_X4(b[pp][0], b[pp][1], b[pp][2], b[pp][3], addr);
            }
            #pragma unroll
            for (int mi = 0; mi < 4; mi++)
                #pragma unroll
                for (int nj = 0; nj < 8; nj++)
                    mma16(acc[mi][nj], a[mi],
                          b[nj >> 1][(nj & 1) * 2], b[nj >> 1][(nj & 1) * 2 + 1]);
        }
    };

    // prologue: stages 0 and 1 in flight
    issue_copy(0, 0); CP_COMMIT();
    issue_copy(1, 1); CP_COMMIT();

    int buf = 0;
    for (int kt = 0; kt < KT; kt++) {
        CP_WAIT1();                       // own copies of stage kt done
        __syncthreads();                  // everyone's copies visible; stage
                                          // (kt-1)%3 reads all retired
        if (kt + 2 < KT) issue_copy(kt + 2, (buf + 2) % NSTAGE);
        CP_COMMIT();                      // keep one group per iteration
        compute(buf);
        buf = (buf + 1) % NSTAGE;
    }

    // ---- epilogue ----
    const int gr0 = bm * 128 + wm * 64 + (lane >> 2);
    const int gc0 = bn * 128 + wn * 64 + (lane & 3) * 2;
    #pragma unroll
    for (int mi = 0; mi < 4; mi++) {
        #pragma unroll
        for (int half = 0; half < 2; half++) {
            const int row = gr0 + mi * 16 + half * 8;
            float rn = 0.f;
            if (EPI == 2) rn = rown[row];
            #pragma unroll
            for (int nj = 0; nj < 8; nj++) {
                const int col = gc0 + nj * 8;
                const float v0 = acc[mi][nj][half * 2 + 0];
                const float v1 = acc[mi][nj][half * 2 + 1];
                if (EPI == 1) {
                    __nv_bfloat16* crow = (__nv_bfloat16*)Cv + (size_t)row * N;
                    const uint32_t pk = pack_bf16(fmaxf(v0 + prm[col + 0], 0.f),
                                                  fmaxf(v1 + prm[col + 1], 0.f));
                    *(uint32_t*)(crow + col) = pk;
                } else {
                    float* crow = (float*)Cv + (size_t)row * N;
                    float d0 = fmaxf(fmaf(-2.f, v0, rn + prm[col + 0]), 0.f);
                    float d1 = fmaxf(fmaf(-2.f, v1, rn + prm[col + 1]), 0.f);
                    float2 o = { -log1pf(d0), -log1pf(d1) };
                    *(float2*)(crow + col) = o;
                }
            }
        }
    }
}

// ---------------------------------------------------------------------------
// fp32 -> bf16 conversion (optional relu). 8 elements per thread.
// ---------------------------------------------------------------------------
template<bool RELU>
__global__ __launch_bounds__(256)
void f2b_kernel(const float* __restrict__ in, __nv_bfloat16* __restrict__ out)
{
    const size_t i = (size_t)blockIdx.x * blockDim.x + threadIdx.x;
    const float4* p = (const float4*)in + i * 2;
    float4 a = p[0], b = p[1];
    if (RELU) {
        a.x = fmaxf(a.x, 0.f); a.y = fmaxf(a.y, 0.f);
        a.z = fmaxf(a.z, 0.f); a.w = fmaxf(a.w, 0.f);
        b.x = fmaxf(b.x, 0.f); b.y = fmaxf(b.y, 0.f);
        b.z = fmaxf(b.z, 0.f); b.w = fmaxf(b.w, 0.f);
    }
    uint4 o = { pack_bf16(a.x, a.y), pack_bf16(a.z, a.w),
                pack_bf16(b.x, b.y), pack_bf16(b.z, b.w) };
    ((uint4*)out)[i] = o;
}

// ---------------------------------------------------------------------------
// Row squared-norm over bf16 rows: one warp per row
// ---------------------------------------------------------------------------
__global__ void rownorm_bf16(const __nv_bfloat16* __restrict__ X,
                             float* __restrict__ out, int rows, int cols)
{
    const int warp = (blockIdx.x * blockDim.x + threadIdx.x) >> 5;
    const int lane = threadIdx.x & 31;
    if (warp >= rows) return;
    const __nv_bfloat162* r = (const __nv_bfloat162*)(X + (size_t)warp * cols);
    float s = 0.f;
    for (int c = lane; c < cols / 2; c += 32) {
        const float2 v = __bfloat1622float2(r[c]);
        s = fmaf(v.x, v.x, fmaf(v.y, v.y, s));
    }
    #pragma unroll
    for (int o = 16; o; o >>= 1) s += __shfl_xor_sync(0xFFFFFFFFu, s, o);
    if (lane == 0) out[warp] = s;
}

// ---------------------------------------------------------------------------
// In-place per-row log-softmax: t -= logsumexp(t). One 256-thr block per row.
// ---------------------------------------------------------------------------
__global__ __launch_bounds__(256)
void lse_kernel(float* __restrict__ T)
{
    __shared__ float rmax[8];
    __shared__ float rsum[8];
    float* t = T + (size_t)blockIdx.x * NY;
    const int tid  = threadIdx.x;
    const int lane = tid & 31;
    const int w    = tid >> 5;

    float v[4];
    float m = -INFINITY;
    #pragma unroll
    for (int i = 0; i < 4; i++) {
        v[i] = t[tid + i * 256];
        m = fmaxf(m, v[i]);
    }
    #pragma unroll
    for (int o = 16; o; o >>= 1) m = fmaxf(m, __shfl_xor_sync(0xFFFFFFFFu, m, o));
    if (lane == 0) rmax[w] = m;
    __syncthreads();
    m = rmax[0];
    #pragma unroll
    for (int i = 1; i < 8; i++) m = fmaxf(m, rmax[i]);

    float s = 0.f;
    #pragma unroll
    for (int i = 0; i < 4; i++) s += expf(v[i] - m);
    #pragma unroll
    for (int o = 16; o; o >>= 1) s += __shfl_xor_sync(0xFFFFFFFFu, s, o);
    if (lane == 0) rsum[w] = s;
    __syncthreads();
    float tot = rsum[0];
    #pragma unroll
    for (int i = 1; i < 8; i++) tot += rsum[i];

    const float lse = m + logf(tot);
    #pragma unroll
    for (int i = 0; i < 4; i++) t[tid + i * 256] = v[i] - lse;
}

// ---------------------------------------------------------------------------
extern "C" void kernel_launch(void* const* d_in, const int* in_sizes, int n_in,
                              void* d_out, int out_size)
{
    const float* x    = (const float*)d_in[0];   // [B, Nx]
    const float* W_fc = (const float*)d_in[1];   // [Nh, Nx]
    const float* b_fc = (const float*)d_in[2];   // [Nh]
    const float* W_q  = (const float*)d_in[3];   // [Ny, Nh]
    float* out = (float*)d_out;                  // [B, Ny]

    void* p;
    cudaGetSymbolAddress(&p, g_xb);     __nv_bfloat16* xb   = (__nv_bfloat16*)p;
    cudaGetSymbolAddress(&p, g_wfcb);   __nv_bfloat16* wfcb = (__nv_bfloat16*)p;
    cudaGetSymbolAddress(&p, g_wqb);    __nv_bfloat16* wqb  = (__nv_bfloat16*)p;
    cudaGetSymbolAddress(&p, g_hb);     __nv_bfloat16* hb   = (__nv_bfloat16*)p;
    cudaGetSymbolAddress(&p, g_hnorm);  float* hn  = (float*)p;
    cudaGetSymbolAddress(&p, g_wqnorm); float* wqn = (float*)p;

    cudaFuncSetAttribute(tgemm<1>, cudaFuncAttributeMaxDynamicSharedMemorySize, DSMEM_BYTES);
    cudaFuncSetAttribute(tgemm<2>, cudaFuncAttributeMaxDynamicSharedMemorySize, DSMEM_BYTES);

    // 0) convert inputs to bf16 (relu fused into x)
    f2b_kernel<true> <<<(size_t)BB * NX / 2048, 256>>>(x,    xb);
    f2b_kernel<false><<<(size_t)NH * NX / 2048, 256>>>(W_fc, wfcb);
    f2b_kernel<false><<<(size_t)NY * NH / 2048, 256>>>(W_q,  wqb);

    // 1) h = relu(xb @ wfcb^T + b_fc)  -> bf16
    {
        dim3 grid(NH / 128, BB / 128);
        tgemm<1><<<grid, 128, DSMEM_BYTES>>>(xb, wfcb, b_fc, nullptr, hb, BB, NH, NX);
    }
    // 2) row norms (from the same bf16 values the GEMM consumes)
    rownorm_bf16<<<(BB * 32 + 255) / 256, 256>>>(hb,  hn,  BB, NH);
    rownorm_bf16<<<(NY * 32 + 255) / 256, 256>>>(wqb, wqn, NY, NH);

    // 3) t = -log1p(max(||h||^2 - 2 h@W_q^T + ||w||^2, 0))
    {
        dim3 grid(NY / 128, BB / 128);
        tgemm<2><<<grid, 128, DSMEM_BYTES>>>(hb, wqb, wqn, hn, out, BB, NY, NH);
    }
    // 4) log-softmax normalization per row
    lse_kernel<<<BB, 256>>>(out);
}

// round 9
// speedup vs baseline: 1.0410x; 1.0410x over previous
#include <cuda_runtime.h>
#include <cuda_bf16.h>
#include <math.h>
#include <stdint.h>

#define BB   8192
#define NX   2048
#define NH   512
#define NY   1024

// Scratch (no allocations allowed in kernel_launch)
__device__ __nv_bfloat16 g_xb[(size_t)BB * NX];    // relu(x) in bf16
__device__ __nv_bfloat16 g_wfcb[(size_t)NH * NX];  // W_fc in bf16
__device__ __nv_bfloat16 g_wqb[(size_t)NY * NH];   // W_q in bf16
__device__ __nv_bfloat16 g_hb[(size_t)BB * NH];    // hidden activations bf16
__device__ float g_hpart[(size_t)BB * 8];          // per-(row, coltile) sum h^2
__device__ float g_hnorm[BB];                      // ||h_i||^2
__device__ float g_wqnorm[NY];                     // ||w_j||^2

// ---------------------------------------------------------------------------
static __device__ __forceinline__ uint32_t smem_u32(const void* p) {
    uint32_t a;
    asm("{ .reg .u64 t; cvta.to.shared.u64 t, %1; cvt.u32.u64 %0, t; }"
        : "=r"(a) : "l"(p));
    return a;
}

#define LDSM_X4(r0, r1, r2, r3, a)                                           \
    asm volatile("ldmatrix.sync.aligned.m8n8.x4.shared.b16 {%0,%1,%2,%3}, [%4];" \
                 : "=r"(r0), "=r"(r1), "=r"(r2), "=r"(r3) : "r"(a))

#define CP16(s, g)                                                           \
    asm volatile("cp.async.cg.shared.global [%0], [%1], 16;" :: "r"(s), "l"(g))
#define CP_COMMIT() asm volatile("cp.async.commit_group;" ::: "memory")
#define CP_WAIT1()  asm volatile("cp.async.wait_group 1;"  ::: "memory")

static __device__ __forceinline__ void mma16(float* c, const uint32_t* a,
                                             uint32_t b0, uint32_t b1) {
    asm volatile(
        "mma.sync.aligned.m16n8k16.row.col.f32.bf16.bf16.f32 "
        "{%0,%1,%2,%3}, {%4,%5,%6,%7}, {%8,%9}, {%0,%1,%2,%3};"
        : "+f"(c[0]), "+f"(c[1]), "+f"(c[2]), "+f"(c[3])
        : "r"(a[0]), "r"(a[1]), "r"(a[2]), "r"(a[3]), "r"(b0), "r"(b1));
}

static __device__ __forceinline__ uint32_t pack_bf16(float lo, float hi) {
    __nv_bfloat162 v = __floats2bfloat162_rn(lo, hi);  // .x = low half
    return *(uint32_t*)&v;
}

// ---------------------------------------------------------------------------
// bf16 mma.sync GEMM-NT, cp.async 3-stage pipeline, 4 warps, warp tile 64x64.
// C[m][n] = epi( sum_k A[m][k] * B[n][k] ), A/B bf16 K-major.
// CTA tile 128x128, BK=64 (128B rows, SW128 swizzle), warps 2m x 2n.
// MSUB M-tiles processed per CTA (tail-wave removal).
// EPI==1: C(bf16) = relu(acc + prm[n]); also writes per-row partial sum of
//         bf16(h)^2 into hpart[row*8 + bn*2 + wn].
// EPI==2: C(f32)  = -log1p(max(rown[m] - 2*acc + prm[n], 0))
// ---------------------------------------------------------------------------
#define TILE_BYTES  16384               // 128 rows x 128B
#define STAGE_BYTES 32768               // A + B
#define NSTAGE      3
#define DSMEM_BYTES (NSTAGE * STAGE_BYTES)

template<int EPI, int MSUB>
__global__ __launch_bounds__(128, 2)
void tgemm(const __nv_bfloat16* __restrict__ A, const __nv_bfloat16* __restrict__ Bm,
           const float* __restrict__ prm, const float* __restrict__ rown,
           float* __restrict__ hpart, void* __restrict__ Cv, int M, int N, int K)
{
    extern __shared__ char smem[];
    const uint32_t sbase = smem_u32(smem);

    const int tid  = threadIdx.x;
    const int bn   = blockIdx.x;
    const int warp = tid >> 5, lane = tid & 31;
    const int wm   = warp & 1;          // 0..1 : 64-row slice
    const int wn   = warp >> 1;         // 0..1 : 64-col slice
    const int rm   = lane & 7;

    const int kha = lane >> 4;
    const int khb = (lane >> 3) & 1;
    int rowA[4], rowB[4];
    #pragma unroll
    for (int mi = 0; mi < 4; mi++)
        rowA[mi] = wm * 64 + mi * 16 + ((lane >> 3) & 1) * 8 + rm;
    #pragma unroll
    for (int pp = 0; pp < 4; pp++)
        rowB[pp] = wn * 64 + pp * 16 + ((lane >> 4) & 1) * 8 + rm;

    const int KT = K >> 6;              // chunks of BK=64
    const int r0 = tid >> 3;            // loader row base
    const int c4 = tid & 7;             // loader 16B chunk

    for (int sub = 0; sub < MSUB; sub++) {
        const int bm = blockIdx.y * MSUB + sub;
        __syncthreads();                // protect stage buffers across subs

        float acc[4][8][4];
        #pragma unroll
        for (int i = 0; i < 4; i++)
            #pragma unroll
            for (int j = 0; j < 8; j++)
                #pragma unroll
                for (int q = 0; q < 4; q++) acc[i][j][q] = 0.f;

        auto issue_copy = [&](int kt, int buf) {
            const uint32_t sa = sbase + buf * STAGE_BYTES;
            const uint32_t sb = sa + TILE_BYTES;
            const __nv_bfloat16* ag = A  + (size_t)(bm * 128 + r0) * K + kt * 64 + c4 * 8;
            const __nv_bfloat16* bg = Bm + (size_t)(bn * 128 + r0) * K + kt * 64 + c4 * 8;
            #pragma unroll
            for (int p = 0; p < 8; p++) {
                const int row = r0 + p * 16;
                const uint32_t soff = row * 128 + ((c4 ^ (row & 7)) * 16);
                CP16(sa + soff, ag + (size_t)p * 16 * K);
                CP16(sb + soff, bg + (size_t)p * 16 * K);
            }
        };

        auto compute = [&](int buf) {
            const uint32_t Sa = sbase + buf * STAGE_BYTES;
            const uint32_t Sb = Sa + TILE_BYTES;
            #pragma unroll
            for (int ks = 0; ks < 4; ks++) {
                uint32_t a[4][4], b[4][4];
                #pragma unroll
                for (int mi = 0; mi < 4; mi++) {
                    const uint32_t addr = Sa + rowA[mi] * 128 + (((2*ks + kha) ^ rm) * 16);
                    LDSM_X4(a[mi][0], a[mi][1], a[mi][2], a[mi][3], addr);
                }
                #pragma unroll
                for (int pp = 0; pp < 4; pp++) {
                    const uint32_t addr = Sb + rowB[pp] * 128 + (((2*ks + khb) ^ rm) * 16);
                    LDSM_X4(b[pp][0], b[pp][1], b[pp][2], b[pp][3], addr);
                }
                #pragma unroll
                for (int mi = 0; mi < 4; mi++)
                    #pragma unroll
                    for (int nj = 0; nj < 8; nj++)
                        mma16(acc[mi][nj], a[mi],
                              b[nj >> 1][(nj & 1) * 2], b[nj >> 1][(nj & 1) * 2 + 1]);
            }
        };

        issue_copy(0, 0); CP_COMMIT();
        issue_copy(1, 1); CP_COMMIT();

        int buf = 0;
        for (int kt = 0; kt < KT; kt++) {
            CP_WAIT1();
            __syncthreads();
            if (kt + 2 < KT) issue_copy(kt + 2, (buf + 2) % NSTAGE);
            CP_COMMIT();
            compute(buf);
            buf = (buf + 1) % NSTAGE;
        }

        // ---- epilogue ----
        const int gr0 = bm * 128 + wm * 64 + (lane >> 2);
        const int gc0 = bn * 128 + wn * 64 + (lane & 3) * 2;
        #pragma unroll
        for (int mi = 0; mi < 4; mi++) {
            #pragma unroll
            for (int half = 0; half < 2; half++) {
                const int row = gr0 + mi * 16 + half * 8;
                float rn = 0.f;
                if (EPI == 2) rn = rown[row];
                float s = 0.f;                 // partial sum of bf16(h)^2
                #pragma unroll
                for (int nj = 0; nj < 8; nj++) {
                    const int col = gc0 + nj * 8;
                    const float v0 = acc[mi][nj][half * 2 + 0];
                    const float v1 = acc[mi][nj][half * 2 + 1];
                    if (EPI == 1) {
                        __nv_bfloat16* crow = (__nv_bfloat16*)Cv + (size_t)row * N;
                        const __nv_bfloat162 hp = __floats2bfloat162_rn(
                            fmaxf(v0 + prm[col + 0], 0.f),
                            fmaxf(v1 + prm[col + 1], 0.f));
                        *(uint32_t*)(crow + col) = *(const uint32_t*)&hp;
                        const float2 hf = __bfloat1622float2(hp);
                        s = fmaf(hf.x, hf.x, fmaf(hf.y, hf.y, s));
                    } else {
                        float* crow = (float*)Cv + (size_t)row * N;
                        float d0 = fmaxf(fmaf(-2.f, v0, rn + prm[col + 0]), 0.f);
                        float d1 = fmaxf(fmaf(-2.f, v1, rn + prm[col + 1]), 0.f);
                        float2 o = { -log1pf(d0), -log1pf(d1) };
                        *(float2*)(crow + col) = o;
                    }
                }
                if (EPI == 1) {
                    // reduce s over the 4 lanes sharing this row (lane&3)
                    s += __shfl_xor_sync(0xFFFFFFFFu, s, 1);
                    s += __shfl_xor_sync(0xFFFFFFFFu, s, 2);
                    if ((lane & 3) == 0)
                        hpart[(size_t)row * 8 + bn * 2 + wn] = s;
                }
            }
        }
    }
}

// ---------------------------------------------------------------------------
// Merged fp32->bf16 conversion: x (relu), W_fc, W_q. 8 elems/thread.
// Region boundaries are multiples of 2048, so blocks never straddle regions.
// ---------------------------------------------------------------------------
#define NXB_E ((size_t)BB * NX)
#define NFC_E ((size_t)NH * NX)
#define NWQ_E ((size_t)NY * NH)

__global__ __launch_bounds__(256)
void convert_all(const float* __restrict__ x, const float* __restrict__ wfc,
                 const float* __restrict__ wq, __nv_bfloat16* __restrict__ xb,
                 __nv_bfloat16* __restrict__ wfcb, __nv_bfloat16* __restrict__ wqb)
{
    const size_t i = (size_t)blockIdx.x * blockDim.x + threadIdx.x;
    const size_t e = i * 8;
    const float* src;
    __nv_bfloat16* dst;
    bool relu;
    if (e < NXB_E)              { src = x   + e;                 dst = xb   + e;                 relu = true;  }
    else if (e < NXB_E + NFC_E) { src = wfc + (e - NXB_E);       dst = wfcb + (e - NXB_E);       relu = false; }
    else                        { src = wq  + (e - NXB_E - NFC_E); dst = wqb + (e - NXB_E - NFC_E); relu = false; }

    float4 a = ((const float4*)src)[0];
    float4 b = ((const float4*)src)[1];
    if (relu) {
        a.x = fmaxf(a.x, 0.f); a.y = fmaxf(a.y, 0.f);
        a.z = fmaxf(a.z, 0.f); a.w = fmaxf(a.w, 0.f);
        b.x = fmaxf(b.x, 0.f); b.y = fmaxf(b.y, 0.f);
        b.z = fmaxf(b.z, 0.f); b.w = fmaxf(b.w, 0.f);
    }
    uint4 o = { pack_bf16(a.x, a.y), pack_bf16(a.z, a.w),
                pack_bf16(b.x, b.y), pack_bf16(b.z, b.w) };
    *(uint4*)dst = o;
}

// ---------------------------------------------------------------------------
// hnorm[r] = sum of 8 per-coltile partials
// ---------------------------------------------------------------------------
__global__ __launch_bounds__(256)
void norm_finish(const float* __restrict__ part, float* __restrict__ out)
{
    const int r = blockIdx.x * blockDim.x + threadIdx.x;
    const float4* p = (const float4*)(part + (size_t)r * 8);
    const float4 a = p[0], b = p[1];
    out[r] = ((a.x + a.y) + (a.z + a.w)) + ((b.x + b.y) + (b.z + b.w));
}

// ---------------------------------------------------------------------------
// Row squared-norm over bf16 rows: one warp per row (used for W_q)
// ---------------------------------------------------------------------------
__global__ void rownorm_bf16(const __nv_bfloat16* __restrict__ X,
                             float* __restrict__ out, int rows, int cols)
{
    const int warp = (blockIdx.x * blockDim.x + threadIdx.x) >> 5;
    const int lane = threadIdx.x & 31;
    if (warp >= rows) return;
    const __nv_bfloat162* r = (const __nv_bfloat162*)(X + (size_t)warp * cols);
    float s = 0.f;
    for (int c = lane; c < cols / 2; c += 32) {
        const float2 v = __bfloat1622float2(r[c]);
        s = fmaf(v.x, v.x, fmaf(v.y, v.y, s));
    }
    #pragma unroll
    for (int o = 16; o; o >>= 1) s += __shfl_xor_sync(0xFFFFFFFFu, s, o);
    if (lane == 0) out[warp] = s;
}

// ---------------------------------------------------------------------------
// In-place per-row log-softmax: t -= logsumexp(t). One 256-thr block per row.
// ---------------------------------------------------------------------------
__global__ __launch_bounds__(256)
void lse_kernel(float* __restrict__ T)
{
    __shared__ float rmax[8];
    __shared__ float rsum[8];
    float* t = T + (size_t)blockIdx.x * NY;
    const int tid  = threadIdx.x;
    const int lane = tid & 31;
    const int w    = tid >> 5;

    const float4 v = *(const float4*)(t + tid * 4);
    float m = fmaxf(fmaxf(v.x, v.y), fmaxf(v.z, v.w));
    #pragma unroll
    for (int o = 16; o; o >>= 1) m = fmaxf(m, __shfl_xor_sync(0xFFFFFFFFu, m, o));
    if (lane == 0) rmax[w] = m;
    __syncthreads();
    m = rmax[0];
    #pragma unroll
    for (int i = 1; i < 8; i++) m = fmaxf(m, rmax[i]);

    float s = expf(v.x - m) + expf(v.y - m) + expf(v.z - m) + expf(v.w - m);
    #pragma unroll
    for (int o = 16; o; o >>= 1) s += __shfl_xor_sync(0xFFFFFFFFu, s, o);
    if (lane == 0) rsum[w] = s;
    __syncthreads();
    float tot = rsum[0];
    #pragma unroll
    for (int i = 1; i < 8; i++) tot += rsum[i];

    const float lse = m + logf(tot);
    float4 o4 = { v.x - lse, v.y - lse, v.z - lse, v.w - lse };
    *(float4*)(t + tid * 4) = o4;
}

// ---------------------------------------------------------------------------
extern "C" void kernel_launch(void* const* d_in, const int* in_sizes, int n_in,
                              void* d_out, int out_size)
{
    const float* x    = (const float*)d_in[0];   // [B, Nx]
    const float* W_fc = (const float*)d_in[1];   // [Nh, Nx]
    const float* b_fc = (const float*)d_in[2];   // [Nh]
    const float* W_q  = (const float*)d_in[3];   // [Ny, Nh]
    float* out = (float*)d_out;                  // [B, Ny]

    void* p;
    cudaGetSymbolAddress(&p, g_xb);     __nv_bfloat16* xb   = (__nv_bfloat16*)p;
    cudaGetSymbolAddress(&p, g_wfcb);   __nv_bfloat16* wfcb = (__nv_bfloat16*)p;
    cudaGetSymbolAddress(&p, g_wqb);    __nv_bfloat16* wqb  = (__nv_bfloat16*)p;
    cudaGetSymbolAddress(&p, g_hb);     __nv_bfloat16* hb   = (__nv_bfloat16*)p;
    cudaGetSymbolAddress(&p, g_hpart);  float* hp  = (float*)p;
    cudaGetSymbolAddress(&p, g_hnorm);  float* hn  = (float*)p;
    cudaGetSymbolAddress(&p, g_wqnorm); float* wqn = (float*)p;

    cudaFuncSetAttribute(tgemm<1, 1>, cudaFuncAttributeMaxDynamicSharedMemorySize, DSMEM_BYTES);
    cudaFuncSetAttribute(tgemm<2, 2>, cudaFuncAttributeMaxDynamicSharedMemorySize, DSMEM_BYTES);

    // 0) convert all inputs to bf16 (relu fused into x) — one kernel
    {
        const size_t total = NXB_E + NFC_E + NWQ_E;
        convert_all<<<(unsigned)(total / 2048), 256>>>(x, W_fc, W_q, xb, wfcb, wqb);
    }
    // 0b) W_q row norms (tiny)
    rownorm_bf16<<<(NY * 32 + 255) / 256, 256>>>(wqb, wqn, NY, NH);

    // 1) h = relu(xb @ wfcb^T + b_fc) -> bf16, plus ||h||^2 partials
    {
        dim3 grid(NH / 128, BB / 128);
        tgemm<1, 1><<<grid, 128, DSMEM_BYTES>>>(xb, wfcb, b_fc, nullptr, hp, hb, BB, NH, NX);
    }
    // 1b) finish ||h||^2
    norm_finish<<<BB / 256, 256>>>(hp, hn);

    // 2) t = -log1p(max(||h||^2 - 2 h@W_q^T + ||w||^2, 0)) ; 2 M-tiles/CTA
    {
        dim3 grid(NY / 128, BB / 256);
        tgemm<2, 2><<<grid, 128, DSMEM_BYTES>>>(hb, wqb, wqn, hn, nullptr, out, BB, NY, NH);
    }
    // 3) log-softmax normalization per row
    lse_kernel<<<BB, 256>>>(out);
}

// round 10
// speedup vs baseline: 1.0427x; 1.0016x over previous
#include <cuda_runtime.h>
#include <cuda_bf16.h>
#include <math.h>
#include <stdint.h>

#define BB   8192
#define NX   2048
#define NH   512
#define NY   1024

// Scratch (no allocations allowed in kernel_launch)
__device__ __nv_bfloat16 g_xb[(size_t)BB * NX];    // relu(x) in bf16
__device__ __nv_bfloat16 g_wfcb[(size_t)NH * NX];  // W_fc in bf16
__device__ __nv_bfloat16 g_wqb[(size_t)NY * NH];   // W_q in bf16
__device__ __nv_bfloat16 g_hb[(size_t)BB * NH];    // hidden activations bf16
__device__ float g_hpart[(size_t)BB * 8];          // per-(row, coltile) sum h^2
__device__ float g_wqnorm[NY];                     // ||w_j||^2

// ---------------------------------------------------------------------------
static __device__ __forceinline__ uint32_t smem_u32(const void* p) {
    uint32_t a;
    asm("{ .reg .u64 t; cvta.to.shared.u64 t, %1; cvt.u32.u64 %0, t; }"
        : "=r"(a) : "l"(p));
    return a;
}

#define LDSM_X4(r0, r1, r2, r3, a)                                           \
    asm volatile("ldmatrix.sync.aligned.m8n8.x4.shared.b16 {%0,%1,%2,%3}, [%4];" \
                 : "=r"(r0), "=r"(r1), "=r"(r2), "=r"(r3) : "r"(a))

#define CP16(s, g)                                                           \
    asm volatile("cp.async.cg.shared.global [%0], [%1], 16;" :: "r"(s), "l"(g))
#define CP_COMMIT() asm volatile("cp.async.commit_group;" ::: "memory")
#define CP_WAIT1()  asm volatile("cp.async.wait_group 1;"  ::: "memory")

static __device__ __forceinline__ void mma16(float* c, const uint32_t* a,
                                             uint32_t b0, uint32_t b1) {
    asm volatile(
        "mma.sync.aligned.m16n8k16.row.col.f32.bf16.bf16.f32 "
        "{%0,%1,%2,%3}, {%4,%5,%6,%7}, {%8,%9}, {%0,%1,%2,%3};"
        : "+f"(c[0]), "+f"(c[1]), "+f"(c[2]), "+f"(c[3])
        : "r"(a[0]), "r"(a[1]), "r"(a[2]), "r"(a[3]), "r"(b0), "r"(b1));
}

static __device__ __forceinline__ uint32_t pack_bf16(float lo, float hi) {
    __nv_bfloat162 v = __floats2bfloat162_rn(lo, hi);  // .x = low half
    return *(uint32_t*)&v;
}

// ---------------------------------------------------------------------------
// bf16 mma.sync GEMM-NT, cp.async 3-stage pipeline, 4 warps, warp tile 64x64.
// C[m][n] = epi( sum_k A[m][k] * B[n][k] ), A/B bf16 K-major.
// CTA tile 128x128, BK=64 (128B rows, SW128 swizzle), warps 2m x 2n.
// MSUB M-tiles processed per CTA (tail-wave removal).
// EPI==1: C(bf16) = relu(acc + prm[n]); writes per-row partial sum of
//         bf16(h)^2 into hpart[row*8 + bn*2 + wn].
// EPI==2: C(f32)  = -log1p(max(rown[m] - 2*acc + prm[n], 0)) where rown is
//         reduced in-kernel from hpart (8 partials/row) into smem.
// ---------------------------------------------------------------------------
#define TILE_BYTES  16384               // 128 rows x 128B
#define STAGE_BYTES 32768               // A + B
#define NSTAGE      3
#define DSMEM_BYTES (NSTAGE * STAGE_BYTES + 512)

template<int EPI, int MSUB>
__global__ __launch_bounds__(128, 2)
void tgemm(const __nv_bfloat16* __restrict__ A, const __nv_bfloat16* __restrict__ Bm,
           const float* __restrict__ prm, const float* __restrict__ hpart,
           void* __restrict__ Cv, int M, int N, int K)
{
    extern __shared__ char smem[];
    const uint32_t sbase = smem_u32(smem);
    float* rn_s = (float*)(smem + NSTAGE * STAGE_BYTES);   // 128 floats

    const int tid  = threadIdx.x;
    const int bn   = blockIdx.x;
    const int warp = tid >> 5, lane = tid & 31;
    const int wm   = warp & 1;          // 0..1 : 64-row slice
    const int wn   = warp >> 1;         // 0..1 : 64-col slice
    const int rm   = lane & 7;

    const int kha = lane >> 4;
    const int khb = (lane >> 3) & 1;
    int rowA[4], rowB[4];
    #pragma unroll
    for (int mi = 0; mi < 4; mi++)
        rowA[mi] = wm * 64 + mi * 16 + ((lane >> 3) & 1) * 8 + rm;
    #pragma unroll
    for (int pp = 0; pp < 4; pp++)
        rowB[pp] = wn * 64 + pp * 16 + ((lane >> 4) & 1) * 8 + rm;

    const int KT = K >> 6;              // chunks of BK=64
    const int r0 = tid >> 3;            // loader row base
    const int c4 = tid & 7;             // loader 16B chunk

    for (int sub = 0; sub < MSUB; sub++) {
        const int bm = blockIdx.y * MSUB + sub;
        __syncthreads();                // protect stage buffers + rn_s reuse

        // fused ||h||^2 finish: one row per thread (tid < 128 always true)
        if (EPI == 2) {
            const float4* pp = (const float4*)(hpart + (size_t)(bm * 128 + tid) * 8);
            const float4 a = pp[0], b = pp[1];
            rn_s[tid] = ((a.x + a.y) + (a.z + a.w)) + ((b.x + b.y) + (b.z + b.w));
        }

        float acc[4][8][4];
        #pragma unroll
        for (int i = 0; i < 4; i++)
            #pragma unroll
            for (int j = 0; j < 8; j++)
                #pragma unroll
                for (int q = 0; q < 4; q++) acc[i][j][q] = 0.f;

        auto issue_copy = [&](int kt, int buf) {
            const uint32_t sa = sbase + buf * STAGE_BYTES;
            const uint32_t sb = sa + TILE_BYTES;
            const __nv_bfloat16* ag = A  + (size_t)(bm * 128 + r0) * K + kt * 64 + c4 * 8;
            const __nv_bfloat16* bg = Bm + (size_t)(bn * 128 + r0) * K + kt * 64 + c4 * 8;
            #pragma unroll
            for (int p = 0; p < 8; p++) {
                const int row = r0 + p * 16;
                const uint32_t soff = row * 128 + ((c4 ^ (row & 7)) * 16);
                CP16(sa + soff, ag + (size_t)p * 16 * K);
                CP16(sb + soff, bg + (size_t)p * 16 * K);
            }
        };

        auto compute = [&](int buf) {
            const uint32_t Sa = sbase + buf * STAGE_BYTES;
            const uint32_t Sb = Sa + TILE_BYTES;
            #pragma unroll
            for (int ks = 0; ks < 4; ks++) {
                uint32_t a[4][4], b[4][4];
                #pragma unroll
                for (int mi = 0; mi < 4; mi++) {
                    const uint32_t addr = Sa + rowA[mi] * 128 + (((2*ks + kha) ^ rm) * 16);
                    LDSM_X4(a[mi][0], a[mi][1], a[mi][2], a[mi][3], addr);
                }
                #pragma unroll
                for (int pp = 0; pp < 4; pp++) {
                    const uint32_t addr = Sb + rowB[pp] * 128 + (((2*ks + khb) ^ rm) * 16);
                    LDSM_X4(b[pp][0], b[pp][1], b[pp][2], b[pp][3], addr);
                }
                #pragma unroll
                for (int mi = 0; mi < 4; mi++)
                    #pragma unroll
                    for (int nj = 0; nj < 8; nj++)
                        mma16(acc[mi][nj], a[mi],
                              b[nj >> 1][(nj & 1) * 2], b[nj >> 1][(nj & 1) * 2 + 1]);
            }
        };

        issue_copy(0, 0); CP_COMMIT();
        issue_copy(1, 1); CP_COMMIT();

        int buf = 0;
        for (int kt = 0; kt < KT; kt++) {
            CP_WAIT1();
            __syncthreads();            // also orders rn_s writes before epilogue
            if (kt + 2 < KT) issue_copy(kt + 2, (buf + 2) % NSTAGE);
            CP_COMMIT();
            compute(buf);
            buf = (buf + 1) % NSTAGE;
        }

        // ---- epilogue ----
        const int lr0 = wm * 64 + (lane >> 2);          // local row in tile
        const int gc0 = bn * 128 + wn * 64 + (lane & 3) * 2;
        #pragma unroll
        for (int mi = 0; mi < 4; mi++) {
            #pragma unroll
            for (int half = 0; half < 2; half++) {
                const int lrow = lr0 + mi * 16 + half * 8;
                const int row  = bm * 128 + lrow;
                float rn = 0.f;
                if (EPI == 2) rn = rn_s[lrow];
                float s = 0.f;                 // partial sum of bf16(h)^2
                #pragma unroll
                for (int nj = 0; nj < 8; nj++) {
                    const int col = gc0 + nj * 8;
                    const float v0 = acc[mi][nj][half * 2 + 0];
                    const float v1 = acc[mi][nj][half * 2 + 1];
                    if (EPI == 1) {
                        __nv_bfloat16* crow = (__nv_bfloat16*)Cv + (size_t)row * N;
                        const __nv_bfloat162 hp = __floats2bfloat162_rn(
                            fmaxf(v0 + prm[col + 0], 0.f),
                            fmaxf(v1 + prm[col + 1], 0.f));
                        *(uint32_t*)(crow + col) = *(const uint32_t*)&hp;
                        const float2 hf = __bfloat1622float2(hp);
                        s = fmaf(hf.x, hf.x, fmaf(hf.y, hf.y, s));
                    } else {
                        float* crow = (float*)Cv + (size_t)row * N;
                        float d0 = fmaxf(fmaf(-2.f, v0, rn + prm[col + 0]), 0.f);
                        float d1 = fmaxf(fmaf(-2.f, v1, rn + prm[col + 1]), 0.f);
                        float2 o = { -log1pf(d0), -log1pf(d1) };
                        *(float2*)(crow + col) = o;
                    }
                }
                if (EPI == 1) {
                    s += __shfl_xor_sync(0xFFFFFFFFu, s, 1);
                    s += __shfl_xor_sync(0xFFFFFFFFu, s, 2);
                    if ((lane & 3) == 0)
                        ((float*)prm, (void)0), // no-op to keep template simple
                        g_hpart[(size_t)row * 8 + bn * 2 + wn] = s;
                }
            }
        }
    }
}

// ---------------------------------------------------------------------------
// Merged fp32->bf16 conversion: x (relu), W_fc, W_q. 8 elems/thread.
// Region boundaries are multiples of 2048, so blocks never straddle regions.
// ---------------------------------------------------------------------------
#define NXB_E ((size_t)BB * NX)
#define NFC_E ((size_t)NH * NX)
#define NWQ_E ((size_t)NY * NH)

__global__ __launch_bounds__(256)
void convert_all(const float* __restrict__ x, const float* __restrict__ wfc,
                 const float* __restrict__ wq, __nv_bfloat16* __restrict__ xb,
                 __nv_bfloat16* __restrict__ wfcb, __nv_bfloat16* __restrict__ wqb)
{
    const size_t i = (size_t)blockIdx.x * blockDim.x + threadIdx.x;
    const size_t e = i * 8;
    const float* src;
    __nv_bfloat16* dst;
    bool relu;
    if (e < NXB_E)              { src = x   + e;                 dst = xb   + e;                 relu = true;  }
    else if (e < NXB_E + NFC_E) { src = wfc + (e - NXB_E);       dst = wfcb + (e - NXB_E);       relu = false; }
    else                        { src = wq  + (e - NXB_E - NFC_E); dst = wqb + (e - NXB_E - NFC_E); relu = false; }

    float4 a = ((const float4*)src)[0];
    float4 b = ((const float4*)src)[1];
    if (relu) {
        a.x = fmaxf(a.x, 0.f); a.y = fmaxf(a.y, 0.f);
        a.z = fmaxf(a.z, 0.f); a.w = fmaxf(a.w, 0.f);
        b.x = fmaxf(b.x, 0.f); b.y = fmaxf(b.y, 0.f);
        b.z = fmaxf(b.z, 0.f); b.w = fmaxf(b.w, 0.f);
    }
    uint4 o = { pack_bf16(a.x, a.y), pack_bf16(a.z, a.w),
                pack_bf16(b.x, b.y), pack_bf16(b.z, b.w) };
    *(uint4*)dst = o;
}

// ---------------------------------------------------------------------------
// Row squared-norm over bf16 rows: one warp per row (used for W_q)
// ---------------------------------------------------------------------------
__global__ void rownorm_bf16(const __nv_bfloat16* __restrict__ X,
                             float* __restrict__ out, int rows, int cols)
{
    const int warp = (blockIdx.x * blockDim.x + threadIdx.x) >> 5;
    const int lane = threadIdx.x & 31;
    if (warp >= rows) return;
    const __nv_bfloat162* r = (const __nv_bfloat162*)(X + (size_t)warp * cols);
    float s = 0.f;
    for (int c = lane; c < cols / 2; c += 32) {
        const float2 v = __bfloat1622float2(r[c]);
        s = fmaf(v.x, v.x, fmaf(v.y, v.y, s));
    }
    #pragma unroll
    for (int o = 16; o; o >>= 1) s += __shfl_xor_sync(0xFFFFFFFFu, s, o);
    if (lane == 0) out[warp] = s;
}

// ---------------------------------------------------------------------------
// In-place per-row log-softmax: t -= logsumexp(t). One 256-thr block per row.
// ---------------------------------------------------------------------------
__global__ __launch_bounds__(256)
void lse_kernel(float* __restrict__ T)
{
    __shared__ float rmax[8];
    __shared__ float rsum[8];
    float* t = T + (size_t)blockIdx.x * NY;
    const int tid  = threadIdx.x;
    const int lane = tid & 31;
    const int w    = tid >> 5;

    const float4 v = *(const float4*)(t + tid * 4);
    float m = fmaxf(fmaxf(v.x, v.y), fmaxf(v.z, v.w));
    #pragma unroll
    for (int o = 16; o; o >>= 1) m = fmaxf(m, __shfl_xor_sync(0xFFFFFFFFu, m, o));
    if (lane == 0) rmax[w] = m;
    __syncthreads();
    m = rmax[0];
    #pragma unroll
    for (int i = 1; i < 8; i++) m = fmaxf(m, rmax[i]);

    float s = expf(v.x - m) + expf(v.y - m) + expf(v.z - m) + expf(v.w - m);
    #pragma unroll
    for (int o = 16; o; o >>= 1) s += __shfl_xor_sync(0xFFFFFFFFu, s, o);
    if (lane == 0) rsum[w] = s;
    __syncthreads();
    float tot = rsum[0];
    #pragma unroll
    for (int i = 1; i < 8; i++) tot += rsum[i];

    const float lse = m + logf(tot);
    float4 o4 = { v.x - lse, v.y - lse, v.z - lse, v.w - lse };
    *(float4*)(t + tid * 4) = o4;
}

// ---------------------------------------------------------------------------
extern "C" void kernel_launch(void* const* d_in, const int* in_sizes, int n_in,
                              void* d_out, int out_size)
{
    const float* x    = (const float*)d_in[0];   // [B, Nx]
    const float* W_fc = (const float*)d_in[1];   // [Nh, Nx]
    const float* b_fc = (const float*)d_in[2];   // [Nh]
    const float* W_q  = (const float*)d_in[3];   // [Ny, Nh]
    float* out = (float*)d_out;                  // [B, Ny]

    void* p;
    cudaGetSymbolAddress(&p, g_xb);     __nv_bfloat16* xb   = (__nv_bfloat16*)p;
    cudaGetSymbolAddress(&p, g_wfcb);   __nv_bfloat16* wfcb = (__nv_bfloat16*)p;
    cudaGetSymbolAddress(&p, g_wqb);    __nv_bfloat16* wqb  = (__nv_bfloat16*)p;
    cudaGetSymbolAddress(&p, g_hb);     __nv_bfloat16* hb   = (__nv_bfloat16*)p;
    cudaGetSymbolAddress(&p, g_hpart);  float* hp  = (float*)p;
    cudaGetSymbolAddress(&p, g_wqnorm); float* wqn = (float*)p;

    cudaFuncSetAttribute(tgemm<1, 1>, cudaFuncAttributeMaxDynamicSharedMemorySize, DSMEM_BYTES);
    cudaFuncSetAttribute(tgemm<2, 2>, cudaFuncAttributeMaxDynamicSharedMemorySize, DSMEM_BYTES);

    // 0) convert all inputs to bf16 (relu fused into x) — one kernel
    {
        const size_t total = NXB_E + NFC_E + NWQ_E;
        convert_all<<<(unsigned)(total / 2048), 256>>>(x, W_fc, W_q, xb, wfcb, wqb);
    }
    // 0b) W_q row norms (tiny)
    rownorm_bf16<<<(NY * 32 + 255) / 256, 256>>>(wqb, wqn, NY, NH);

    // 1) h = relu(xb @ wfcb^T + b_fc) -> bf16, plus ||h||^2 partials
    {
        dim3 grid(NH / 128, BB / 128);
        tgemm<1, 1><<<grid, 128, DSMEM_BYTES>>>(xb, wfcb, b_fc, hp, hb, BB, NH, NX);
    }
    // 2) t = -log1p(max(||h||^2 - 2 h@W_q^T + ||w||^2, 0)) ; 2 M-tiles/CTA
    //    (||h||^2 finished in-kernel from partials)
    {
        dim3 grid(NY / 128, BB / 256);
        tgemm<2, 2><<<grid, 128, DSMEM_BYTES>>>(hb, wqb, wqn, hp, out, BB, NY, NH);
    }
    // 3) log-softmax normalization per row
    lse_kernel<<<BB, 256>>>(out);
}

// round 11
// speedup vs baseline: 1.1177x; 1.0720x over previous
#include <cuda_runtime.h>
#include <cuda_bf16.h>
#include <math.h>
#include <stdint.h>

#define BB   8192
#define NX   2048
#define NH   512
#define NY   1024

// Scratch (no allocations allowed in kernel_launch)
__device__ __nv_bfloat16 g_xb[(size_t)BB * NX];    // relu(x) in bf16
__device__ __nv_bfloat16 g_wfcb[(size_t)NH * NX];  // W_fc in bf16
__device__ __nv_bfloat16 g_wqb[(size_t)NY * NH];   // W_q in bf16
__device__ __nv_bfloat16 g_hb[(size_t)BB * NH];    // hidden activations bf16
__device__ float g_hpart[(size_t)BB * 8];          // per-(row, coltile) sum h^2
__device__ float g_wqnorm[NY];                     // ||w_j||^2

// ---------------------------------------------------------------------------
static __device__ __forceinline__ uint32_t smem_u32(const void* p) {
    uint32_t a;
    asm("{ .reg .u64 t; cvta.to.shared.u64 t, %1; cvt.u32.u64 %0, t; }"
        : "=r"(a) : "l"(p));
    return a;
}

#define LDSM_X4(r0, r1, r2, r3, a)                                           \
    asm volatile("ldmatrix.sync.aligned.m8n8.x4.shared.b16 {%0,%1,%2,%3}, [%4];" \
                 : "=r"(r0), "=r"(r1), "=r"(r2), "=r"(r3) : "r"(a))

#define CP16(s, g)                                                           \
    asm volatile("cp.async.cg.shared.global [%0], [%1], 16;" :: "r"(s), "l"(g))
#define CP_COMMIT() asm volatile("cp.async.commit_group;" ::: "memory")
#define CP_WAIT1()  asm volatile("cp.async.wait_group 1;"  ::: "memory")

static __device__ __forceinline__ void mma16(float* c, const uint32_t* a,
                                             uint32_t b0, uint32_t b1) {
    asm volatile(
        "mma.sync.aligned.m16n8k16.row.col.f32.bf16.bf16.f32 "
        "{%0,%1,%2,%3}, {%4,%5,%6,%7}, {%8,%9}, {%0,%1,%2,%3};"
        : "+f"(c[0]), "+f"(c[1]), "+f"(c[2]), "+f"(c[3])
        : "r"(a[0]), "r"(a[1]), "r"(a[2]), "r"(a[3]), "r"(b0), "r"(b1));
}

static __device__ __forceinline__ uint32_t pack_bf16(float lo, float hi) {
    __nv_bfloat162 v = __floats2bfloat162_rn(lo, hi);  // .x = low half
    return *(uint32_t*)&v;
}

#define TILE_BYTES  16384               // 128 rows x 128B
#define STAGE_BYTES 32768               // A + B
#define NSTAGE      3
#define DSMEM_BYTES (NSTAGE * STAGE_BYTES + 512)

// ---------------------------------------------------------------------------
// GEMM1: h = relu(A@B^T + bias), 4 warps, warp tile 64x64, CTA 128x128, BK=64.
// Writes bf16 h and per-row partial sums of bf16(h)^2 into hpart.
// ---------------------------------------------------------------------------
__global__ __launch_bounds__(128, 2)
void tgemm1(const __nv_bfloat16* __restrict__ A, const __nv_bfloat16* __restrict__ Bm,
            const float* __restrict__ prm, float* __restrict__ hpart,
            __nv_bfloat16* __restrict__ C, int M, int N, int K)
{
    extern __shared__ char smem[];
    const uint32_t sbase = smem_u32(smem);

    const int tid  = threadIdx.x;
    const int bn   = blockIdx.x, bm = blockIdx.y;
    const int warp = tid >> 5, lane = tid & 31;
    const int wm   = warp & 1;
    const int wn   = warp >> 1;         // 0..1
    const int rm   = lane & 7;

    const int kha = lane >> 4;
    const int khb = (lane >> 3) & 1;
    int rowA[4], rowB[4];
    #pragma unroll
    for (int mi = 0; mi < 4; mi++)
        rowA[mi] = wm * 64 + mi * 16 + ((lane >> 3) & 1) * 8 + rm;
    #pragma unroll
    for (int pp = 0; pp < 4; pp++)
        rowB[pp] = wn * 64 + pp * 16 + ((lane >> 4) & 1) * 8 + rm;

    float acc[4][8][4];
    #pragma unroll
    for (int i = 0; i < 4; i++)
        #pragma unroll
        for (int j = 0; j < 8; j++)
            #pragma unroll
            for (int q = 0; q < 4; q++) acc[i][j][q] = 0.f;

    const int KT = K >> 6;
    const int r0 = tid >> 3;
    const int c4 = tid & 7;

    auto issue_copy = [&](int kt, int buf) {
        const uint32_t sa = sbase + buf * STAGE_BYTES;
        const uint32_t sb = sa + TILE_BYTES;
        const __nv_bfloat16* ag = A  + (size_t)(bm * 128 + r0) * K + kt * 64 + c4 * 8;
        const __nv_bfloat16* bg = Bm + (size_t)(bn * 128 + r0) * K + kt * 64 + c4 * 8;
        #pragma unroll
        for (int p = 0; p < 8; p++) {
            const int row = r0 + p * 16;
            const uint32_t soff = row * 128 + ((c4 ^ (row & 7)) * 16);
            CP16(sa + soff, ag + (size_t)p * 16 * K);
            CP16(sb + soff, bg + (size_t)p * 16 * K);
        }
    };

    auto compute = [&](int buf) {
        const uint32_t Sa = sbase + buf * STAGE_BYTES;
        const uint32_t Sb = Sa + TILE_BYTES;
        #pragma unroll
        for (int ks = 0; ks < 4; ks++) {
            uint32_t a[4][4], b[4][4];
            #pragma unroll
            for (int mi = 0; mi < 4; mi++) {
                const uint32_t addr = Sa + rowA[mi] * 128 + (((2*ks + kha) ^ rm) * 16);
                LDSM_X4(a[mi][0], a[mi][1], a[mi][2], a[mi][3], addr);
            }
            #pragma unroll
            for (int pp = 0; pp < 4; pp++) {
                const uint32_t addr = Sb + rowB[pp] * 128 + (((2*ks + khb) ^ rm) * 16);
                LDSM_X4(b[pp][0], b[pp][1], b[pp][2], b[pp][3], addr);
            }
            #pragma unroll
            for (int mi = 0; mi < 4; mi++)
                #pragma unroll
                for (int nj = 0; nj < 8; nj++)
                    mma16(acc[mi][nj], a[mi],
                          b[nj >> 1][(nj & 1) * 2], b[nj >> 1][(nj & 1) * 2 + 1]);
        }
    };

    issue_copy(0, 0); CP_COMMIT();
    issue_copy(1, 1); CP_COMMIT();
    int buf = 0;
    for (int kt = 0; kt < KT; kt++) {
        CP_WAIT1();
        __syncthreads();
        if (kt + 2 < KT) issue_copy(kt + 2, (buf + 2) % NSTAGE);
        CP_COMMIT();
        compute(buf);
        buf = (buf + 1) % NSTAGE;
    }

    const int gr0 = bm * 128 + wm * 64 + (lane >> 2);
    const int gc0 = bn * 128 + wn * 64 + (lane & 3) * 2;
    #pragma unroll
    for (int mi = 0; mi < 4; mi++) {
        #pragma unroll
        for (int half = 0; half < 2; half++) {
            const int row = gr0 + mi * 16 + half * 8;
            float s = 0.f;
            #pragma unroll
            for (int nj = 0; nj < 8; nj++) {
                const int col = gc0 + nj * 8;
                const float v0 = acc[mi][nj][half * 2 + 0];
                const float v1 = acc[mi][nj][half * 2 + 1];
                const __nv_bfloat162 hp = __floats2bfloat162_rn(
                    fmaxf(v0 + prm[col + 0], 0.f),
                    fmaxf(v1 + prm[col + 1], 0.f));
                *(uint32_t*)(C + (size_t)row * N + col) = *(const uint32_t*)&hp;
                const float2 hf = __bfloat1622float2(hp);
                s = fmaf(hf.x, hf.x, fmaf(hf.y, hf.y, s));
            }
            s += __shfl_xor_sync(0xFFFFFFFFu, s, 1);
            s += __shfl_xor_sync(0xFFFFFFFFu, s, 2);
            if ((lane & 3) == 0)
                hpart[(size_t)row * 8 + bn * 2 + wn] = s;
        }
    }
}

// ---------------------------------------------------------------------------
// GEMM2: t = -log(1 + max(||h||^2 - 2 h@Wq^T + ||w||^2, 0))
// 8 warps (2m x 4n, warp tile 64x32), CTA 128x128, MSUB=2 M-tiles per CTA.
// ||h||^2 finished in-kernel from hpart into smem.
// ---------------------------------------------------------------------------
#define MSUB2 2
__global__ __launch_bounds__(256, 2)
void tgemm2(const __nv_bfloat16* __restrict__ A, const __nv_bfloat16* __restrict__ Bm,
            const float* __restrict__ prm, const float* __restrict__ hpart,
            float* __restrict__ C, int M, int N, int K)
{
    extern __shared__ char smem[];
    const uint32_t sbase = smem_u32(smem);
    float* rn_s = (float*)(smem + NSTAGE * STAGE_BYTES);   // 128 floats

    const int tid  = threadIdx.x;
    const int bn   = blockIdx.x;
    const int warp = tid >> 5, lane = tid & 31;
    const int wm   = warp & 1;          // 0..1 : 64-row slice
    const int wn   = warp >> 1;         // 0..3 : 32-col slice
    const int rm   = lane & 7;

    const int kha = lane >> 4;
    const int khb = (lane >> 3) & 1;
    int rowA[4], rowB[2];
    #pragma unroll
    for (int mi = 0; mi < 4; mi++)
        rowA[mi] = wm * 64 + mi * 16 + ((lane >> 3) & 1) * 8 + rm;
    #pragma unroll
    for (int pp = 0; pp < 2; pp++)
        rowB[pp] = wn * 32 + pp * 16 + ((lane >> 4) & 1) * 8 + rm;

    const int KT = K >> 6;
    const int r0 = tid >> 3;            // 0..31
    const int c4 = tid & 7;

    for (int sub = 0; sub < MSUB2; sub++) {
        const int bm = blockIdx.y * MSUB2 + sub;
        __syncthreads();                // protect stage buffers + rn_s

        if (tid < 128) {
            const float4* pp = (const float4*)(hpart + (size_t)(bm * 128 + tid) * 8);
            const float4 a = pp[0], b = pp[1];
            rn_s[tid] = ((a.x + a.y) + (a.z + a.w)) + ((b.x + b.y) + (b.z + b.w));
        }

        float acc[4][4][4];
        #pragma unroll
        for (int i = 0; i < 4; i++)
            #pragma unroll
            for (int j = 0; j < 4; j++)
                #pragma unroll
                for (int q = 0; q < 4; q++) acc[i][j][q] = 0.f;

        auto issue_copy = [&](int kt, int buf) {
            const uint32_t sa = sbase + buf * STAGE_BYTES;
            const uint32_t sb = sa + TILE_BYTES;
            const __nv_bfloat16* ag = A  + (size_t)(bm * 128 + r0) * K + kt * 64 + c4 * 8;
            const __nv_bfloat16* bg = Bm + (size_t)(bn * 128 + r0) * K + kt * 64 + c4 * 8;
            #pragma unroll
            for (int p = 0; p < 4; p++) {
                const int row = r0 + p * 32;
                const uint32_t soff = row * 128 + ((c4 ^ (row & 7)) * 16);
                CP16(sa + soff, ag + (size_t)p * 32 * K);
                CP16(sb + soff, bg + (size_t)p * 32 * K);
            }
        };

        auto compute = [&](int buf) {
            const uint32_t Sa = sbase + buf * STAGE_BYTES;
            const uint32_t Sb = Sa + TILE_BYTES;
            #pragma unroll
            for (int ks = 0; ks < 4; ks++) {
                uint32_t a[4][4], b[2][4];
                #pragma unroll
                for (int mi = 0; mi < 4; mi++) {
                    const uint32_t addr = Sa + rowA[mi] * 128 + (((2*ks + kha) ^ rm) * 16);
                    LDSM_X4(a[mi][0], a[mi][1], a[mi][2], a[mi][3], addr);
                }
                #pragma unroll
                for (int pp = 0; pp < 2; pp++) {
                    const uint32_t addr = Sb + rowB[pp] * 128 + (((2*ks + khb) ^ rm) * 16);
                    LDSM_X4(b[pp][0], b[pp][1], b[pp][2], b[pp][3], addr);
                }
                #pragma unroll
                for (int mi = 0; mi < 4; mi++)
                    #pragma unroll
                    for (int nj = 0; nj < 4; nj++)
                        mma16(acc[mi][nj], a[mi],
                              b[nj >> 1][(nj & 1) * 2], b[nj >> 1][(nj & 1) * 2 + 1]);
            }
        };

        issue_copy(0, 0); CP_COMMIT();
        issue_copy(1, 1); CP_COMMIT();
        int buf = 0;
        for (int kt = 0; kt < KT; kt++) {
            CP_WAIT1();
            __syncthreads();            // also orders rn_s before epilogue
            if (kt + 2 < KT) issue_copy(kt + 2, (buf + 2) % NSTAGE);
            CP_COMMIT();
            compute(buf);
            buf = (buf + 1) % NSTAGE;
        }

        const int lr0 = wm * 64 + (lane >> 2);
        const int gc0 = bn * 128 + wn * 32 + (lane & 3) * 2;
        #pragma unroll
        for (int mi = 0; mi < 4; mi++) {
            #pragma unroll
            for (int half = 0; half < 2; half++) {
                const int lrow = lr0 + mi * 16 + half * 8;
                const int row  = bm * 128 + lrow;
                const float rn = rn_s[lrow];
                float* crow = C + (size_t)row * N;
                #pragma unroll
                for (int nj = 0; nj < 4; nj++) {
                    const int col = gc0 + nj * 8;
                    const float v0 = acc[mi][nj][half * 2 + 0];
                    const float v1 = acc[mi][nj][half * 2 + 1];
                    const float d0 = fmaxf(fmaf(-2.f, v0, rn + prm[col + 0]), 0.f);
                    const float d1 = fmaxf(fmaf(-2.f, v1, rn + prm[col + 1]), 0.f);
                    float2 o = { -__logf(1.f + d0), -__logf(1.f + d1) };
                    *(float2*)(crow + col) = o;
                }
            }
        }
    }
}

// ---------------------------------------------------------------------------
// Merged fp32->bf16 conversion: x (relu), W_fc, W_q. 8 elems/thread.
// ---------------------------------------------------------------------------
#define NXB_E ((size_t)BB * NX)
#define NFC_E ((size_t)NH * NX)
#define NWQ_E ((size_t)NY * NH)

__global__ __launch_bounds__(256)
void convert_all(const float* __restrict__ x, const float* __restrict__ wfc,
                 const float* __restrict__ wq, __nv_bfloat16* __restrict__ xb,
                 __nv_bfloat16* __restrict__ wfcb, __nv_bfloat16* __restrict__ wqb)
{
    const size_t i = (size_t)blockIdx.x * blockDim.x + threadIdx.x;
    const size_t e = i * 8;
    const float* src;
    __nv_bfloat16* dst;
    bool relu;
    if (e < NXB_E)              { src = x   + e;                 dst = xb   + e;                 relu = true;  }
    else if (e < NXB_E + NFC_E) { src = wfc + (e - NXB_E);       dst = wfcb + (e - NXB_E);       relu = false; }
    else                        { src = wq  + (e - NXB_E - NFC_E); dst = wqb + (e - NXB_E - NFC_E); relu = false; }

    float4 a = ((const float4*)src)[0];
    float4 b = ((const float4*)src)[1];
    if (relu) {
        a.x = fmaxf(a.x, 0.f); a.y = fmaxf(a.y, 0.f);
        a.z = fmaxf(a.z, 0.f); a.w = fmaxf(a.w, 0.f);
        b.x = fmaxf(b.x, 0.f); b.y = fmaxf(b.y, 0.f);
        b.z = fmaxf(b.z, 0.f); b.w = fmaxf(b.w, 0.f);
    }
    uint4 o = { pack_bf16(a.x, a.y), pack_bf16(a.z, a.w),
                pack_bf16(b.x, b.y), pack_bf16(b.z, b.w) };
    *(uint4*)dst = o;
}

// ---------------------------------------------------------------------------
// Row squared-norm over bf16 rows: one warp per row (used for W_q)
// ---------------------------------------------------------------------------
__global__ void rownorm_bf16(const __nv_bfloat16* __restrict__ X,
                             float* __restrict__ out, int rows, int cols)
{
    const int warp = (blockIdx.x * blockDim.x + threadIdx.x) >> 5;
    const int lane = threadIdx.x & 31;
    if (warp >= rows) return;
    const __nv_bfloat162* r = (const __nv_bfloat162*)(X + (size_t)warp * cols);
    float s = 0.f;
    for (int c = lane; c < cols / 2; c += 32) {
        const float2 v = __bfloat1622float2(r[c]);
        s = fmaf(v.x, v.x, fmaf(v.y, v.y, s));
    }
    #pragma unroll
    for (int o = 16; o; o >>= 1) s += __shfl_xor_sync(0xFFFFFFFFu, s, o);
    if (lane == 0) out[warp] = s;
}

// ---------------------------------------------------------------------------
// In-place per-row log-softmax: t -= logsumexp(t). One 256-thr block per row.
// ---------------------------------------------------------------------------
__global__ __launch_bounds__(256)
void lse_kernel(float* __restrict__ T)
{
    __shared__ float rmax[8];
    __shared__ float rsum[8];
    float* t = T + (size_t)blockIdx.x * NY;
    const int tid  = threadIdx.x;
    const int lane = tid & 31;
    const int w    = tid >> 5;

    const float4 v = *(const float4*)(t + tid * 4);
    float m = fmaxf(fmaxf(v.x, v.y), fmaxf(v.z, v.w));
    #pragma unroll
    for (int o = 16; o; o >>= 1) m = fmaxf(m, __shfl_xor_sync(0xFFFFFFFFu, m, o));
    if (lane == 0) rmax[w] = m;
    __syncthreads();
    m = rmax[0];
    #pragma unroll
    for (int i = 1; i < 8; i++) m = fmaxf(m, rmax[i]);

    float s = __expf(v.x - m) + __expf(v.y - m) + __expf(v.z - m) + __expf(v.w - m);
    #pragma unroll
    for (int o = 16; o; o >>= 1) s += __shfl_xor_sync(0xFFFFFFFFu, s, o);
    if (lane == 0) rsum[w] = s;
    __syncthreads();
    float tot = rsum[0];
    #pragma unroll
    for (int i = 1; i < 8; i++) tot += rsum[i];

    const float lse = m + logf(tot);
    float4 o4 = { v.x - lse, v.y - lse, v.z - lse, v.w - lse };
    *(float4*)(t + tid * 4) = o4;
}

// ---------------------------------------------------------------------------
extern "C" void kernel_launch(void* const* d_in, const int* in_sizes, int n_in,
                              void* d_out, int out_size)
{
    const float* x    = (const float*)d_in[0];   // [B, Nx]
    const float* W_fc = (const float*)d_in[1];   // [Nh, Nx]
    const float* b_fc = (const float*)d_in[2];   // [Nh]
    const float* W_q  = (const float*)d_in[3];   // [Ny, Nh]
    float* out = (float*)d_out;                  // [B, Ny]

    void* p;
    cudaGetSymbolAddress(&p, g_xb);     __nv_bfloat16* xb   = (__nv_bfloat16*)p;
    cudaGetSymbolAddress(&p, g_wfcb);   __nv_bfloat16* wfcb = (__nv_bfloat16*)p;
    cudaGetSymbolAddress(&p, g_wqb);    __nv_bfloat16* wqb  = (__nv_bfloat16*)p;
    cudaGetSymbolAddress(&p, g_hb);     __nv_bfloat16* hb   = (__nv_bfloat16*)p;
    cudaGetSymbolAddress(&p, g_hpart);  float* hp  = (float*)p;
    cudaGetSymbolAddress(&p, g_wqnorm); float* wqn = (float*)p;

    cudaFuncSetAttribute(tgemm1, cudaFuncAttributeMaxDynamicSharedMemorySize, DSMEM_BYTES);
    cudaFuncSetAttribute(tgemm2, cudaFuncAttributeMaxDynamicSharedMemorySize, DSMEM_BYTES);

    // 0) convert all inputs to bf16 (relu fused into x) — one kernel
    {
        const size_t total = NXB_E + NFC_E + NWQ_E;
        convert_all<<<(unsigned)(total / 2048), 256>>>(x, W_fc, W_q, xb, wfcb, wqb);
    }
    // 0b) W_q row norms (tiny)
    rownorm_bf16<<<(NY * 32 + 255) / 256, 256>>>(wqb, wqn, NY, NH);

    // 1) h = relu(xb @ wfcb^T + b_fc) -> bf16, plus ||h||^2 partials
    {
        dim3 grid(NH / 128, BB / 128);
        tgemm1<<<grid, 128, DSMEM_BYTES>>>(xb, wfcb, b_fc, hp, hb, BB, NH, NX);
    }
    // 2) t = -log(1 + max(||h||^2 - 2 h@Wq^T + ||w||^2, 0)) ; 2 M-tiles/CTA
    {
        dim3 grid(NY / 128, BB / 256);
        tgemm2<<<grid, 256, DSMEM_BYTES>>>(hb, wqb, wqn, hp, out, BB, NY, NH);
    }
    // 3) log-softmax normalization per row
    lse_kernel<<<BB, 256>>>(out);
}